// round 10
// baseline (speedup 1.0000x reference)
#include <cuda_runtime.h>
#include <cuda_bf16.h>
#include <cstdint>
#include <cstddef>

// ---------------------------------------------------------------------------
// PWEMoE (B=8,S=2048,H=1024,F=4096,E=8, fp32):
//   g   = mean_s( relu(x@gw1^T + gb1) @ gw2^T ) + gb2
//   mW1 = W1 + sum_e g TW1 ; mb1 = b1 + g@Tb1   (per batch)
//   mW2 = W2 + sum_e g TW2 ; mb2 = b2 + g@Tb2
//   u   = gelu_tanh(x @ mW1^T + mb1) ; out = u @ mW2^T + mb2
//
// .target sm_103 (no 'a') -> tcgen05 unavailable; GEMMs use base-ISA
// mma.sync.m16n8k16 (bf16, fp32 accum), bf16 hi/lo split, 3 passes.
// R10: CTA tile widened to 128(M) x 256(N), 512 threads (16 warps, 4x4),
// same 32x64 warp tile + 2-stage cp.async pipeline as the passing R9 core.
// ---------------------------------------------------------------------------

constexpr int Bsz = 8, S = 2048, H = 1024, F = 4096, E = 8;
constexpr int KC  = 64;                 // bf16 K elems per chunk (128B rows)

// ---- scratch (__device__ globals; allocation is forbidden) ----
__device__ __nv_bfloat16 g_xh[(size_t)Bsz * S * H];
__device__ __nv_bfloat16 g_xl[(size_t)Bsz * S * H];
__device__ __nv_bfloat16 g_gw1h[(size_t)H * H];
__device__ __nv_bfloat16 g_gw1l[(size_t)H * H];
__device__ __nv_bfloat16 g_w1h[(size_t)Bsz * F * H];
__device__ __nv_bfloat16 g_w1l[(size_t)Bsz * F * H];
__device__ __nv_bfloat16 g_w2h[(size_t)Bsz * H * F];
__device__ __nv_bfloat16 g_w2l[(size_t)Bsz * H * F];
__device__ __nv_bfloat16 g_uh[(size_t)Bsz * S * F];
__device__ __nv_bfloat16 g_ul[(size_t)Bsz * S * F];
__device__ float g_partial[Bsz * 128 * E];
__device__ float g_g[Bsz * E];
__device__ float g_mb1[Bsz * F];
__device__ float g_mb2[Bsz * H];

// ---------------------------------------------------------------------------
__device__ __forceinline__ uint32_t smem_u32(const void* p) {
    uint32_t a;
    asm("{ .reg .u64 t; cvta.to.shared.u64 t, %1; cvt.u32.u64 %0, t; }"
        : "=r"(a) : "l"(p));
    return a;
}
__device__ __forceinline__ uint32_t sw128(uint32_t off) {
    return off ^ ((off >> 3) & 0x70);
}
__device__ __forceinline__ float gelu_tanh(float x) {
    const float c = 0.7978845608028654f;
    float t = tanhf(c * (x + 0.044715f * x * x * x));
    return 0.5f * x * (1.0f + t);
}
__device__ __forceinline__ uint32_t pack2(__nv_bfloat16 a, __nv_bfloat16 b) {
    return ((uint32_t)__bfloat16_as_ushort(b) << 16) |
            (uint32_t)__bfloat16_as_ushort(a);
}
__device__ __forceinline__ void cp16(uint32_t dst, const void* src) {
    asm volatile("cp.async.cg.shared.global [%0], [%1], 16;"
                 :: "r"(dst), "l"(src));
}

// ldmatrix x4: lanes 0-15 -> rows 0-15 @ k-bytes 0-15; lanes 16-31 -> rows
// 0-15 @ k-bytes 16-31. r0=(m0-7,k0-7) r1=(m8-15,k0-7) r2=(m0-7,k8-15)
// r3=(m8-15,k8-15) -- exactly the a0..a3 fragment of mma.m16n8k16.
#define LDSM4(r, addr)                                                         \
    asm volatile("ldmatrix.sync.aligned.m8n8.x4.shared.b16 {%0,%1,%2,%3}, [%4];" \
        : "=r"((r)[0]), "=r"((r)[1]), "=r"((r)[2]), "=r"((r)[3])               \
        : "r"(addr))

// D += A(16x16,row) * B(16x8,col)  bf16 -> f32
#define MMA_BF16(c, a, b0, b1)                                                 \
    asm volatile("mma.sync.aligned.m16n8k16.row.col.f32.bf16.bf16.f32 "        \
        "{%0,%1,%2,%3}, {%4,%5,%6,%7}, {%8,%9}, {%0,%1,%2,%3};"                \
        : "+f"((c)[0]), "+f"((c)[1]), "+f"((c)[2]), "+f"((c)[3])               \
        : "r"((a)[0]), "r"((a)[1]), "r"((a)[2]), "r"((a)[3]), "r"(b0), "r"(b1))

// ---------------------------------------------------------------------------
// mma.sync GEMM: D[m,n] = sum_k A[m,k]*B[n,k] (K-major both sides).
// CTA tile 128x256; 16 warps = 4(m) x 4(n); warp tile 32(m) x 64(n).
// MODE 0: gate A=x(split) B=gw1(split); epi relu -> dot gw2 -> tile partials
// MODE 1: ffn1 A=x(split) B=w1(split);  epi +mb1 -> gelu -> u split (bf16)
// MODE 2: ffn2 A=u(split) B=w2(split);  epi +mb2 -> out fp32
// smem per stage: AH 16KB, AL 16KB, BH 32KB, BL 32KB  (96KB); 2 stages.
// ---------------------------------------------------------------------------
constexpr uint32_t OF_AH = 0, OF_AL = 16384, OF_BH = 32768, OF_BL = 65536;
constexpr uint32_t STAGE_BYTES = 98304;
constexpr uint32_t SMEM_BYTES  = 2 * STAGE_BYTES;     // 192 KB -> 1 CTA/SM

template <int MODE>
__global__ __launch_bounds__(512, 1)
void mma_gemm(const float* __restrict__ gb1,
              const float* __restrict__ gw2,
              float* __restrict__ outp)
{
    constexpr int K = (MODE == 2) ? F : H;
    constexpr int NCH = K / KC;

    extern __shared__ char sm[];
    const uint32_t sb = smem_u32(sm);
    const int tid  = threadIdx.x;
    const int wid  = tid >> 5, lane = tid & 31;
    const int wm   = (wid & 3) * 32;          // warp m offset in tile
    const int wn   = (wid >> 2) * 64;         // warp n offset in tile (0..192)
    const int b     = blockIdx.z;
    const int mBase = blockIdx.y * 128, nBase = blockIdx.x * 256;

    const __nv_bfloat16* Ah = (MODE == 2) ? (g_uh + (size_t)b * S * F)
                                          : (g_xh + (size_t)b * S * H);
    const __nv_bfloat16* Al = (MODE == 2) ? (g_ul + (size_t)b * S * F)
                                          : (g_xl + (size_t)b * S * H);
    const __nv_bfloat16* Bh = (MODE == 0) ? g_gw1h
                            : (MODE == 1) ? (g_w1h + (size_t)b * F * H)
                                          : (g_w2h + (size_t)b * H * F);
    const __nv_bfloat16* Bl = (MODE == 0) ? g_gw1l
                            : (MODE == 1) ? (g_w1l + (size_t)b * F * H)
                                          : (g_w2l + (size_t)b * H * F);

    const __nv_bfloat16* const Asrc[2] = { Ah + (size_t)mBase * K,
                                           Al + (size_t)mBase * K };
    const __nv_bfloat16* const Bsrc[2] = { Bh + (size_t)nBase * K,
                                           Bl + (size_t)nBase * K };

    // per-thread load slot: lrow 0..63 (tid>>3), lc 16B column 0..7
    const int lrow = tid >> 3;
    const int lc   = tid & 7;

    // issue one chunk: A bufs 2 row-groups, B bufs 4 row-groups (12 cp16)
    auto issue = [&](int c0) {
        const int k0 = c0 * KC;
        const uint32_t stg = sb + (uint32_t)(c0 & 1) * STAGE_BYTES;
#pragma unroll
        for (int bi = 0; bi < 2; bi++) {
            const __nv_bfloat16* sp = Asrc[bi] + k0;
            uint32_t dp = stg + (bi ? OF_AL : OF_AH);
#pragma unroll
            for (int it = 0; it < 2; it++) {
                int r = lrow + it * 64;      // 0..127
                cp16(dp + sw128((uint32_t)(r * 128 + lc * 16)),
                     sp + (size_t)r * K + lc * 8);
            }
        }
#pragma unroll
        for (int bi = 0; bi < 2; bi++) {
            const __nv_bfloat16* sp = Bsrc[bi] + k0;
            uint32_t dp = stg + (bi ? OF_BL : OF_BH);
#pragma unroll
            for (int it = 0; it < 4; it++) {
                int r = lrow + it * 64;      // 0..255
                cp16(dp + sw128((uint32_t)(r * 128 + lc * 16)),
                     sp + (size_t)r * K + lc * 8);
            }
        }
        asm volatile("cp.async.commit_group;" ::: "memory");
    };

    float acc[2][8][4];
#pragma unroll
    for (int i = 0; i < 2; i++)
#pragma unroll
        for (int j = 0; j < 8; j++)
#pragma unroll
            for (int q = 0; q < 4; q++) acc[i][j][q] = 0.0f;

    issue(0);
    for (int c0 = 0; c0 < NCH; c0++) {
        if (c0 + 1 < NCH) {
            issue(c0 + 1);
            asm volatile("cp.async.wait_group 1;" ::: "memory");
        } else {
            asm volatile("cp.async.wait_group 0;" ::: "memory");
        }
        __syncthreads();

        const uint32_t stg = sb + (uint32_t)(c0 & 1) * STAGE_BYTES;
        // ---- mma: 4 K16 steps; 3 split passes, pass-major so dependent
        //      MMAs on the same accumulator are >=4 instructions apart ----
#pragma unroll
        for (int ks = 0; ks < 4; ks++) {
            uint32_t ah[2][4], al[2][4];
#pragma unroll
            for (int mt = 0; mt < 2; mt++) {
                int row = wm + mt * 16 + (lane & 15);
                uint32_t off = sw128((uint32_t)(row * 128 + (lane >> 4) * 16 + ks * 32));
                LDSM4(ah[mt], stg + OF_AH + off);
                LDSM4(al[mt], stg + OF_AL + off);
            }
#pragma unroll
            for (int p = 0; p < 4; p++) {
                int row = wn + p * 16 + (lane & 15);
                uint32_t off = sw128((uint32_t)(row * 128 + (lane >> 4) * 16 + ks * 32));
                uint32_t bh[4], bl[4];
                LDSM4(bh, stg + OF_BH + off);
                LDSM4(bl, stg + OF_BL + off);
                // pass 1: Ahi * Bhi  (4 independent accumulators)
#pragma unroll
                for (int mt = 0; mt < 2; mt++) {
                    MMA_BF16(acc[mt][2*p],   ah[mt], bh[0], bh[2]);
                    MMA_BF16(acc[mt][2*p+1], ah[mt], bh[1], bh[3]);
                }
                // pass 2: Ahi * Blo
#pragma unroll
                for (int mt = 0; mt < 2; mt++) {
                    MMA_BF16(acc[mt][2*p],   ah[mt], bl[0], bl[2]);
                    MMA_BF16(acc[mt][2*p+1], ah[mt], bl[1], bl[3]);
                }
                // pass 3: Alo * Bhi
#pragma unroll
                for (int mt = 0; mt < 2; mt++) {
                    MMA_BF16(acc[mt][2*p],   al[mt], bh[0], bh[2]);
                    MMA_BF16(acc[mt][2*p+1], al[mt], bh[1], bh[3]);
                }
            }
        }
        __syncthreads();   // all warps done with stage (c0&1) before refill
    }

    // ---- stage per-tile epilogue constants into (now free) smem ----
    float* bias_s = (float*)sm;                     // 256 floats
    float* gw2_s  = bias_s + 256;                   // E*256 floats (MODE 0)
    float* ws     = gw2_s + E * 256;                // 16 warps x E
    if (MODE == 0) {
        for (int i = tid; i < 256; i += 512) bias_s[i] = gb1[nBase + i];
        for (int i = tid; i < E * 256; i += 512)
            gw2_s[i] = gw2[(i >> 8) * H + nBase + (i & 255)];
    } else {
        const float* mb = (MODE == 1) ? (g_mb1 + (size_t)b * F)
                                      : (g_mb2 + (size_t)b * H);
        for (int i = tid; i < 256; i += 512) bias_s[i] = mb[nBase + i];
    }
    __syncthreads();

    // acc element (mt, nt, reg): m = wm + mt*16 + lane/4 + (reg>=2)*8
    //                            n = wn + nt*8 + 2*(lane&3) + (reg&1)
    if (MODE == 0) {
        float p[E];
#pragma unroll
        for (int e = 0; e < E; e++) p[e] = 0.0f;
#pragma unroll
        for (int mt = 0; mt < 2; mt++)
#pragma unroll
            for (int nt = 0; nt < 8; nt++)
#pragma unroll
                for (int q = 0; q < 4; q++) {
                    int n = wn + nt * 8 + 2 * (lane & 3) + (q & 1);
                    float v = fmaxf(acc[mt][nt][q] + bias_s[n], 0.0f);
#pragma unroll
                    for (int e = 0; e < E; e++)
                        p[e] = fmaf(v, gw2_s[e * 256 + n], p[e]);
                }
#pragma unroll
        for (int e = 0; e < E; e++)
#pragma unroll
            for (int o = 16; o > 0; o >>= 1)
                p[e] += __shfl_xor_sync(0xffffffffu, p[e], o);
        if (lane == 0)
#pragma unroll
            for (int e = 0; e < E; e++) ws[wid * E + e] = p[e];
        __syncthreads();
        if (tid < E) {
            float s = 0.0f;
#pragma unroll
            for (int w = 0; w < 16; w++) s += ws[w * E + tid];
            // tiles per batch: (S/128)=16 x (H/256)=4 = 64
            g_partial[(((size_t)b * 16 + blockIdx.y) * 4 + blockIdx.x) * E + tid] = s;
        }
    } else if (MODE == 1) {
#pragma unroll
        for (int mt = 0; mt < 2; mt++)
#pragma unroll
            for (int rh = 0; rh < 2; rh++) {
                int m = mBase + wm + mt * 16 + (lane >> 2) + rh * 8;
                size_t rowo = (size_t)b * S * F + (size_t)m * F + nBase;
#pragma unroll
                for (int nt = 0; nt < 8; nt++) {
                    int n = wn + nt * 8 + 2 * (lane & 3);
                    float v0 = gelu_tanh(acc[mt][nt][rh * 2 + 0] + bias_s[n]);
                    float v1 = gelu_tanh(acc[mt][nt][rh * 2 + 1] + bias_s[n + 1]);
                    __nv_bfloat16 h0 = __float2bfloat16_rn(v0);
                    __nv_bfloat16 h1 = __float2bfloat16_rn(v1);
                    *(uint32_t*)(g_uh + rowo + n) = pack2(h0, h1);
                    *(uint32_t*)(g_ul + rowo + n) = pack2(
                        __float2bfloat16_rn(v0 - __bfloat162float(h0)),
                        __float2bfloat16_rn(v1 - __bfloat162float(h1)));
                }
            }
    } else {
#pragma unroll
        for (int mt = 0; mt < 2; mt++)
#pragma unroll
            for (int rh = 0; rh < 2; rh++) {
                int m = mBase + wm + mt * 16 + (lane >> 2) + rh * 8;
                float* rowp = outp + (size_t)b * S * H + (size_t)m * H + nBase;
#pragma unroll
                for (int nt = 0; nt < 8; nt++) {
                    int n = wn + nt * 8 + 2 * (lane & 3);
                    *(float2*)(rowp + n) = make_float2(
                        acc[mt][nt][rh * 2 + 0] + bias_s[n],
                        acc[mt][nt][rh * 2 + 1] + bias_s[n + 1]);
                }
            }
    }
}

// ---------------------------------------------------------------------------
// fp32 -> bf16 hi/lo split. WHICH 0: x -> g_xh/g_xl, WHICH 1: gw1 -> g_gw1h/l
// ---------------------------------------------------------------------------
template <int WHICH>
__global__ void split_kernel(const float4* __restrict__ src, int n4)
{
    int i = blockIdx.x * blockDim.x + threadIdx.x;
    if (i >= n4) return;
    uint2* dh = (WHICH == 0) ? (uint2*)g_xh : (uint2*)g_gw1h;
    uint2* dl = (WHICH == 0) ? (uint2*)g_xl : (uint2*)g_gw1l;
    float4 v = src[i];
    __nv_bfloat16 h0 = __float2bfloat16_rn(v.x), h1 = __float2bfloat16_rn(v.y);
    __nv_bfloat16 h2 = __float2bfloat16_rn(v.z), h3 = __float2bfloat16_rn(v.w);
    dh[i] = make_uint2(pack2(h0, h1), pack2(h2, h3));
    dl[i] = make_uint2(
        pack2(__float2bfloat16_rn(v.x - __bfloat162float(h0)),
              __float2bfloat16_rn(v.y - __bfloat162float(h1))),
        pack2(__float2bfloat16_rn(v.z - __bfloat162float(h2)),
              __float2bfloat16_rn(v.w - __bfloat162float(h3))));
}

__global__ void reduce_g_kernel(const float* __restrict__ gb2)
{
    int t = threadIdx.x;
    if (t >= Bsz * E) return;
    int b = t >> 3, e = t & 7;
    float s = 0.0f;
    for (int tile = 0; tile < 64; tile++)
        s += g_partial[((size_t)b * 64 + tile) * E + e];
    g_g[b * E + e] = s / (float)S + gb2[e];
}

template <int WHICH>
__global__ void merge_bias_kernel(const float* __restrict__ base,
                                  const float* __restrict__ T)
{
    constexpr int n = (WHICH == 0) ? F : H;
    int i = blockIdx.x * blockDim.x + threadIdx.x;
    if (i >= n) return;
    float bv = base[i];
    float t[E];
#pragma unroll
    for (int e = 0; e < E; e++) t[e] = T[e * n + i];
#pragma unroll
    for (int b = 0; b < Bsz; b++) {
        float s = bv;
#pragma unroll
        for (int e = 0; e < E; e++) s = fmaf(g_g[b * E + e], t[e], s);
        if (WHICH == 0) g_mb1[b * n + i] = s;
        else            g_mb2[b * n + i] = s;
    }
}

// Merged weights: fp32 accumulate, write bf16 hi/lo split directly.
// Reads each task-vector element once, writes all 8 batches.
template <int WHICH>
__global__ void merge_w_kernel(const float4* __restrict__ Wb,
                               const float4* __restrict__ T, int n4)
{
    __shared__ float gs[Bsz * E];
    if (threadIdx.x < Bsz * E) gs[threadIdx.x] = g_g[threadIdx.x];
    __syncthreads();
    uint2* oh = (WHICH == 0) ? (uint2*)g_w1h : (uint2*)g_w2h;
    uint2* ol = (WHICH == 0) ? (uint2*)g_w1l : (uint2*)g_w2l;
    for (int i = blockIdx.x * blockDim.x + threadIdx.x; i < n4;
         i += gridDim.x * blockDim.x) {
        float4 w = Wb[i];
        float4 t[E];
#pragma unroll
        for (int e = 0; e < E; e++) t[e] = T[(size_t)e * n4 + i];
#pragma unroll
        for (int b = 0; b < Bsz; b++) {
            float4 o = w;
#pragma unroll
            for (int e = 0; e < E; e++) {
                float ge = gs[b * E + e];
                o.x = fmaf(ge, t[e].x, o.x);
                o.y = fmaf(ge, t[e].y, o.y);
                o.z = fmaf(ge, t[e].z, o.z);
                o.w = fmaf(ge, t[e].w, o.w);
            }
            __nv_bfloat16 h0 = __float2bfloat16_rn(o.x), h1 = __float2bfloat16_rn(o.y);
            __nv_bfloat16 h2 = __float2bfloat16_rn(o.z), h3 = __float2bfloat16_rn(o.w);
            oh[(size_t)b * n4 + i] = make_uint2(pack2(h0, h1), pack2(h2, h3));
            ol[(size_t)b * n4 + i] = make_uint2(
                pack2(__float2bfloat16_rn(o.x - __bfloat162float(h0)),
                      __float2bfloat16_rn(o.y - __bfloat162float(h1))),
                pack2(__float2bfloat16_rn(o.z - __bfloat162float(h2)),
                      __float2bfloat16_rn(o.w - __bfloat162float(h3))));
        }
    }
}

// ---------------------------------------------------------------------------
extern "C" void kernel_launch(void* const* d_in, const int* in_sizes, int n_in,
                              void* d_out, int out_size)
{
    const float* x   = (const float*)d_in[0];
    const float* gw1 = (const float*)d_in[1];
    const float* gb1 = (const float*)d_in[2];
    const float* gw2 = (const float*)d_in[3];
    const float* gb2 = (const float*)d_in[4];
    const float* W1  = (const float*)d_in[5];
    const float* b1  = (const float*)d_in[6];
    const float* W2  = (const float*)d_in[7];
    const float* b2  = (const float*)d_in[8];
    const float* TW1 = (const float*)d_in[9];
    const float* Tb1 = (const float*)d_in[10];
    const float* TW2 = (const float*)d_in[11];
    const float* Tb2 = (const float*)d_in[12];
    float* out = (float*)d_out;

    cudaFuncSetAttribute(mma_gemm<0>, cudaFuncAttributeMaxDynamicSharedMemorySize, SMEM_BYTES);
    cudaFuncSetAttribute(mma_gemm<1>, cudaFuncAttributeMaxDynamicSharedMemorySize, SMEM_BYTES);
    cudaFuncSetAttribute(mma_gemm<2>, cudaFuncAttributeMaxDynamicSharedMemorySize, SMEM_BYTES);

    // 0. pre-split x and gw1 to bf16 hi/lo
    int nx4 = Bsz * S * H / 4;
    split_kernel<0><<<(nx4 + 255) / 256, 256>>>((const float4*)x, nx4);
    int ng4 = H * H / 4;
    split_kernel<1><<<(ng4 + 255) / 256, 256>>>((const float4*)gw1, ng4);

    // 1. gate GEMM + fused relu/gw2/tile-reduce epilogue
    mma_gemm<0><<<dim3(H / 256, S / 128, Bsz), 512, SMEM_BYTES>>>(gb1, gw2, nullptr);
    // 2. finalize g[b,e]
    reduce_g_kernel<<<1, 64>>>(gb2);
    // 3. merged biases
    merge_bias_kernel<0><<<F / 256, 256>>>(b1, Tb1);
    merge_bias_kernel<1><<<H / 256, 256>>>(b2, Tb2);
    // 4. merged weights -> bf16 hi/lo (read TW once, write 8 batches)
    merge_w_kernel<0><<<2048, 256>>>((const float4*)W1, (const float4*)TW1, F * H / 4);
    merge_w_kernel<1><<<2048, 256>>>((const float4*)W2, (const float4*)TW2, H * F / 4);
    // 5. u = gelu(x @ mW1^T + mb1), stored pre-split
    mma_gemm<1><<<dim3(F / 256, S / 128, Bsz), 512, SMEM_BYTES>>>(nullptr, nullptr, nullptr);
    // 6. out = u @ mW2^T + mb2
    mma_gemm<2><<<dim3(H / 256, S / 128, Bsz), 512, SMEM_BYTES>>>(nullptr, nullptr, out);
}

// round 13
// speedup vs baseline: 2.7925x; 2.7925x over previous
#include <cuda_runtime.h>
#include <cuda_fp16.h>
#include <cstdint>
#include <cstddef>

// ---------------------------------------------------------------------------
// PWEMoE (B=8,S=2048,H=1024,F=4096,E=8, fp32):
//   g   = mean_s( relu(x@gw1^T + gb1) @ gw2^T ) + gb2
//   mW1 = W1 + sum_e g TW1 ; mb1 = b1 + g@Tb1   (per batch)
//   mW2 = W2 + sum_e g TW2 ; mb2 = b2 + g@Tb2
//   u   = gelu_tanh(x @ mW1^T + mb1) ; out = u @ mW2^T + mb2
//
// .target sm_103 (no 'a') -> tcgen05 unavailable; GEMMs use base-ISA
// mma.sync.m16n8k16.f32.f16.f16.f32, SINGLE PASS (fp16 operands, fp32
// accum). R10 showed the HMMA pipe is the bound -> 3x fewer mma ops than
// the bf16 3-pass split. Operands pre-converted to fp16 by producers.
// Tile = 128(M) x 128(N), 256 thr, 2-stage cp.async pipeline, 2 CTAs/SM.
// ---------------------------------------------------------------------------

constexpr int Bsz = 8, S = 2048, H = 1024, F = 4096, E = 8;
constexpr int KC  = 64;                 // fp16 K elems per chunk (128B rows)

// ---- scratch (__device__ globals; allocation is forbidden) ----
__device__ __half g_xf[(size_t)Bsz * S * H];
__device__ __half g_gw1f[(size_t)H * H];
__device__ __half g_w1f[(size_t)Bsz * F * H];
__device__ __half g_w2f[(size_t)Bsz * H * F];
__device__ __half g_uf[(size_t)Bsz * S * F];
__device__ float g_partial[Bsz * 128 * E];
__device__ float g_g[Bsz * E];
__device__ float g_mb1[Bsz * F];
__device__ float g_mb2[Bsz * H];

// ---------------------------------------------------------------------------
__device__ __forceinline__ uint32_t smem_u32(const void* p) {
    uint32_t a;
    asm("{ .reg .u64 t; cvta.to.shared.u64 t, %1; cvt.u32.u64 %0, t; }"
        : "=r"(a) : "l"(p));
    return a;
}
__device__ __forceinline__ uint32_t sw128(uint32_t off) {
    return off ^ ((off >> 3) & 0x70);
}
__device__ __forceinline__ float gelu_tanh(float x) {
    const float c = 0.7978845608028654f;
    float t = tanhf(c * (x + 0.044715f * x * x * x));
    return 0.5f * x * (1.0f + t);
}
__device__ __forceinline__ uint32_t pack2h(__half a, __half b) {
    return ((uint32_t)__half_as_ushort(b) << 16) |
            (uint32_t)__half_as_ushort(a);
}
__device__ __forceinline__ void cp16(uint32_t dst, const void* src) {
    asm volatile("cp.async.cg.shared.global [%0], [%1], 16;"
                 :: "r"(dst), "l"(src));
}

// ldmatrix x4: lanes 0-15 -> rows 0-15 @ k-bytes 0-15; lanes 16-31 -> rows
// 0-15 @ k-bytes 16-31. r0=(m0-7,k0-7) r1=(m8-15,k0-7) r2=(m0-7,k8-15)
// r3=(m8-15,k8-15) -- exactly the a0..a3 fragment of mma.m16n8k16.
#define LDSM4(r, addr)                                                         \
    asm volatile("ldmatrix.sync.aligned.m8n8.x4.shared.b16 {%0,%1,%2,%3}, [%4];" \
        : "=r"((r)[0]), "=r"((r)[1]), "=r"((r)[2]), "=r"((r)[3])               \
        : "r"(addr))

// D += A(16x16,row) * B(16x8,col)  fp16 -> f32
#define MMA_F16(c, a, b0, b1)                                                  \
    asm volatile("mma.sync.aligned.m16n8k16.row.col.f32.f16.f16.f32 "          \
        "{%0,%1,%2,%3}, {%4,%5,%6,%7}, {%8,%9}, {%0,%1,%2,%3};"                \
        : "+f"((c)[0]), "+f"((c)[1]), "+f"((c)[2]), "+f"((c)[3])               \
        : "r"((a)[0]), "r"((a)[1]), "r"((a)[2]), "r"((a)[3]), "r"(b0), "r"(b1))

// ---------------------------------------------------------------------------
// mma.sync GEMM: D[m,n] = sum_k A[m,k]*B[n,k] (K-major both sides).
// CTA tile 128x128; 8 warps = 4(m) x 2(n); warp tile 32(m) x 64(n).
// MODE 0: gate A=x B=gw1; epi relu -> dot gw2 -> tile partials
// MODE 1: ffn1 A=x B=w1;  epi +mb1 -> gelu -> u (fp16)
// MODE 2: ffn2 A=u B=w2;  epi +mb2 -> out fp32
// smem: 2 stages x (A 16KB + B 16KB) = 64KB -> 2 CTAs/SM.
// ---------------------------------------------------------------------------
constexpr uint32_t OF_A = 0, OF_B = 16384;
constexpr uint32_t STAGE_BYTES = 32768;
constexpr uint32_t SMEM_BYTES  = 2 * STAGE_BYTES;

template <int MODE>
__global__ __launch_bounds__(256, 2)
void mma_gemm(const float* __restrict__ gb1,
              const float* __restrict__ gw2,
              float* __restrict__ outp)
{
    constexpr int K = (MODE == 2) ? F : H;
    constexpr int NCH = K / KC;

    extern __shared__ char sm[];
    const uint32_t sb = smem_u32(sm);
    const int tid  = threadIdx.x;
    const int wid  = tid >> 5, lane = tid & 31;
    const int wm   = (wid & 3) * 32;          // warp m offset in tile
    const int wn   = (wid >> 2) * 64;         // warp n offset in tile
    const int b     = blockIdx.z;
    const int mBase = blockIdx.y * 128, nBase = blockIdx.x * 128;

    const __half* A = (MODE == 2) ? (g_uf + (size_t)b * S * F)
                                  : (g_xf + (size_t)b * S * H);
    const __half* B = (MODE == 0) ? g_gw1f
                    : (MODE == 1) ? (g_w1f + (size_t)b * F * H)
                                  : (g_w2f + (size_t)b * H * F);

    const __half* const srcs[2] = { A + (size_t)mBase * K,
                                    B + (size_t)nBase * K };

    // per-thread load slot: 4 rows x 1 col-16B of each of the 2 buffers
    const int lr = tid >> 3;                  // 0..31 base row group
    const int lc = tid & 7;                   // 16B column

    auto issue = [&](int c0) {
        const int k0 = c0 * KC;
        const uint32_t stg = sb + (uint32_t)(c0 & 1) * STAGE_BYTES;
#pragma unroll
        for (int bi = 0; bi < 2; bi++) {
            const __half* sp = srcs[bi] + k0;
            uint32_t dp = stg + (bi ? OF_B : OF_A);
#pragma unroll
            for (int it = 0; it < 4; it++) {
                int r = lr + it * 32;
                cp16(dp + sw128((uint32_t)(r * 128 + lc * 16)),
                     sp + (size_t)r * K + lc * 8);
            }
        }
        asm volatile("cp.async.commit_group;" ::: "memory");
    };

    float acc[2][8][4];
#pragma unroll
    for (int i = 0; i < 2; i++)
#pragma unroll
        for (int j = 0; j < 8; j++)
#pragma unroll
            for (int q = 0; q < 4; q++) acc[i][j][q] = 0.0f;

    issue(0);
    for (int c0 = 0; c0 < NCH; c0++) {
        if (c0 + 1 < NCH) {
            issue(c0 + 1);
            asm volatile("cp.async.wait_group 1;" ::: "memory");
        } else {
            asm volatile("cp.async.wait_group 0;" ::: "memory");
        }
        __syncthreads();

        const uint32_t stg = sb + (uint32_t)(c0 & 1) * STAGE_BYTES;
#pragma unroll
        for (int ks = 0; ks < 4; ks++) {
            uint32_t ah[2][4];
#pragma unroll
            for (int mt = 0; mt < 2; mt++) {
                int row = wm + mt * 16 + (lane & 15);
                uint32_t off = sw128((uint32_t)(row * 128 + (lane >> 4) * 16 + ks * 32));
                LDSM4(ah[mt], stg + OF_A + off);
            }
#pragma unroll
            for (int p = 0; p < 4; p++) {
                int row = wn + p * 16 + (lane & 15);
                uint32_t off = sw128((uint32_t)(row * 128 + (lane >> 4) * 16 + ks * 32));
                uint32_t bh[4];
                LDSM4(bh, stg + OF_B + off);
#pragma unroll
                for (int mt = 0; mt < 2; mt++) {
                    MMA_F16(acc[mt][2*p],   ah[mt], bh[0], bh[2]);
                    MMA_F16(acc[mt][2*p+1], ah[mt], bh[1], bh[3]);
                }
            }
        }
        __syncthreads();   // all warps done with stage (c0&1) before refill
    }

    // ---- stage per-tile epilogue constants into (now free) smem ----
    float* bias_s = (float*)sm;                     // 128 floats
    float* gw2_s  = bias_s + 128;                   // E*128 floats (MODE 0)
    float* ws     = (float*)(sm + 8192);            // 8 warps x E
    if (MODE == 0) {
        for (int i = tid; i < 128; i += 256) bias_s[i] = gb1[nBase + i];
        for (int i = tid; i < E * 128; i += 256)
            gw2_s[i] = gw2[(i >> 7) * H + nBase + (i & 127)];
    } else {
        const float* mb = (MODE == 1) ? (g_mb1 + (size_t)b * F)
                                      : (g_mb2 + (size_t)b * H);
        for (int i = tid; i < 128; i += 256) bias_s[i] = mb[nBase + i];
    }
    __syncthreads();

    // acc element (mt, nt, reg): m = wm + mt*16 + lane/4 + (reg>=2)*8
    //                            n = wn + nt*8 + 2*(lane&3) + (reg&1)
    if (MODE == 0) {
        float p[E];
#pragma unroll
        for (int e = 0; e < E; e++) p[e] = 0.0f;
#pragma unroll
        for (int mt = 0; mt < 2; mt++)
#pragma unroll
            for (int nt = 0; nt < 8; nt++)
#pragma unroll
                for (int q = 0; q < 4; q++) {
                    int n = wn + nt * 8 + 2 * (lane & 3) + (q & 1);
                    float v = fmaxf(acc[mt][nt][q] + bias_s[n], 0.0f);
#pragma unroll
                    for (int e = 0; e < E; e++)
                        p[e] = fmaf(v, gw2_s[e * 128 + n], p[e]);
                }
#pragma unroll
        for (int e = 0; e < E; e++)
#pragma unroll
            for (int o = 16; o > 0; o >>= 1)
                p[e] += __shfl_xor_sync(0xffffffffu, p[e], o);
        if (lane == 0)
#pragma unroll
            for (int e = 0; e < E; e++) ws[wid * E + e] = p[e];
        __syncthreads();
        if (tid < E) {
            float s = 0.0f;
#pragma unroll
            for (int w = 0; w < 8; w++) s += ws[w * E + tid];
            g_partial[(((size_t)b * 16 + blockIdx.y) * 8 + blockIdx.x) * E + tid] = s;
        }
    } else if (MODE == 1) {
#pragma unroll
        for (int mt = 0; mt < 2; mt++)
#pragma unroll
            for (int rh = 0; rh < 2; rh++) {
                int m = mBase + wm + mt * 16 + (lane >> 2) + rh * 8;
                size_t rowo = (size_t)b * S * F + (size_t)m * F + nBase;
#pragma unroll
                for (int nt = 0; nt < 8; nt++) {
                    int n = wn + nt * 8 + 2 * (lane & 3);
                    float v0 = gelu_tanh(acc[mt][nt][rh * 2 + 0] + bias_s[n]);
                    float v1 = gelu_tanh(acc[mt][nt][rh * 2 + 1] + bias_s[n + 1]);
                    *(uint32_t*)(g_uf + rowo + n) =
                        pack2h(__float2half_rn(v0), __float2half_rn(v1));
                }
            }
    } else {
#pragma unroll
        for (int mt = 0; mt < 2; mt++)
#pragma unroll
            for (int rh = 0; rh < 2; rh++) {
                int m = mBase + wm + mt * 16 + (lane >> 2) + rh * 8;
                float* rowp = outp + (size_t)b * S * H + (size_t)m * H + nBase;
#pragma unroll
                for (int nt = 0; nt < 8; nt++) {
                    int n = wn + nt * 8 + 2 * (lane & 3);
                    *(float2*)(rowp + n) = make_float2(
                        acc[mt][nt][rh * 2 + 0] + bias_s[n],
                        acc[mt][nt][rh * 2 + 1] + bias_s[n + 1]);
                }
            }
    }
}

// ---------------------------------------------------------------------------
// fp32 -> fp16 convert. WHICH 0: x -> g_xf, WHICH 1: gw1 -> g_gw1f
// ---------------------------------------------------------------------------
template <int WHICH>
__global__ void conv_kernel(const float4* __restrict__ src, int n4)
{
    int i = blockIdx.x * blockDim.x + threadIdx.x;
    if (i >= n4) return;
    uint2* d = (WHICH == 0) ? (uint2*)g_xf : (uint2*)g_gw1f;
    float4 v = src[i];
    d[i] = make_uint2(pack2h(__float2half_rn(v.x), __float2half_rn(v.y)),
                      pack2h(__float2half_rn(v.z), __float2half_rn(v.w)));
}

__global__ void reduce_g_kernel(const float* __restrict__ gb2)
{
    int t = threadIdx.x;
    if (t >= Bsz * E) return;
    int b = t >> 3, e = t & 7;
    float s = 0.0f;
    for (int tile = 0; tile < 128; tile++)
        s += g_partial[((size_t)b * 128 + tile) * E + e];
    g_g[b * E + e] = s / (float)S + gb2[e];
}

template <int WHICH>
__global__ void merge_bias_kernel(const float* __restrict__ base,
                                  const float* __restrict__ T)
{
    constexpr int n = (WHICH == 0) ? F : H;
    int i = blockIdx.x * blockDim.x + threadIdx.x;
    if (i >= n) return;
    float bv = base[i];
    float t[E];
#pragma unroll
    for (int e = 0; e < E; e++) t[e] = T[e * n + i];
#pragma unroll
    for (int b = 0; b < Bsz; b++) {
        float s = bv;
#pragma unroll
        for (int e = 0; e < E; e++) s = fmaf(g_g[b * E + e], t[e], s);
        if (WHICH == 0) g_mb1[b * n + i] = s;
        else            g_mb2[b * n + i] = s;
    }
}

// Merged weights: fp32 accumulate, write fp16 directly.
// Reads each task-vector element once, writes all 8 batches.
template <int WHICH>
__global__ void merge_w_kernel(const float4* __restrict__ Wb,
                               const float4* __restrict__ T, int n4)
{
    __shared__ float gs[Bsz * E];
    if (threadIdx.x < Bsz * E) gs[threadIdx.x] = g_g[threadIdx.x];
    __syncthreads();
    uint2* o16 = (WHICH == 0) ? (uint2*)g_w1f : (uint2*)g_w2f;
    for (int i = blockIdx.x * blockDim.x + threadIdx.x; i < n4;
         i += gridDim.x * blockDim.x) {
        float4 w = Wb[i];
        float4 t[E];
#pragma unroll
        for (int e = 0; e < E; e++) t[e] = T[(size_t)e * n4 + i];
#pragma unroll
        for (int b = 0; b < Bsz; b++) {
            float4 o = w;
#pragma unroll
            for (int e = 0; e < E; e++) {
                float ge = gs[b * E + e];
                o.x = fmaf(ge, t[e].x, o.x);
                o.y = fmaf(ge, t[e].y, o.y);
                o.z = fmaf(ge, t[e].z, o.z);
                o.w = fmaf(ge, t[e].w, o.w);
            }
            o16[(size_t)b * n4 + i] = make_uint2(
                pack2h(__float2half_rn(o.x), __float2half_rn(o.y)),
                pack2h(__float2half_rn(o.z), __float2half_rn(o.w)));
        }
    }
}

// ---------------------------------------------------------------------------
extern "C" void kernel_launch(void* const* d_in, const int* in_sizes, int n_in,
                              void* d_out, int out_size)
{
    const float* x   = (const float*)d_in[0];
    const float* gw1 = (const float*)d_in[1];
    const float* gb1 = (const float*)d_in[2];
    const float* gw2 = (const float*)d_in[3];
    const float* gb2 = (const float*)d_in[4];
    const float* W1  = (const float*)d_in[5];
    const float* b1  = (const float*)d_in[6];
    const float* W2  = (const float*)d_in[7];
    const float* b2  = (const float*)d_in[8];
    const float* TW1 = (const float*)d_in[9];
    const float* Tb1 = (const float*)d_in[10];
    const float* TW2 = (const float*)d_in[11];
    const float* Tb2 = (const float*)d_in[12];
    float* out = (float*)d_out;

    cudaFuncSetAttribute(mma_gemm<0>, cudaFuncAttributeMaxDynamicSharedMemorySize, SMEM_BYTES);
    cudaFuncSetAttribute(mma_gemm<1>, cudaFuncAttributeMaxDynamicSharedMemorySize, SMEM_BYTES);
    cudaFuncSetAttribute(mma_gemm<2>, cudaFuncAttributeMaxDynamicSharedMemorySize, SMEM_BYTES);

    // 0. pre-convert x and gw1 to fp16
    int nx4 = Bsz * S * H / 4;
    conv_kernel<0><<<(nx4 + 255) / 256, 256>>>((const float4*)x, nx4);
    int ng4 = H * H / 4;
    conv_kernel<1><<<(ng4 + 255) / 256, 256>>>((const float4*)gw1, ng4);

    // 1. gate GEMM + fused relu/gw2/tile-reduce epilogue
    mma_gemm<0><<<dim3(H / 128, S / 128, Bsz), 256, SMEM_BYTES>>>(gb1, gw2, nullptr);
    // 2. finalize g[b,e]
    reduce_g_kernel<<<1, 64>>>(gb2);
    // 3. merged biases
    merge_bias_kernel<0><<<F / 256, 256>>>(b1, Tb1);
    merge_bias_kernel<1><<<H / 256, 256>>>(b2, Tb2);
    // 4. merged weights -> fp16 (read TW once, write 8 batches)
    merge_w_kernel<0><<<2048, 256>>>((const float4*)W1, (const float4*)TW1, F * H / 4);
    merge_w_kernel<1><<<2048, 256>>>((const float4*)W2, (const float4*)TW2, H * F / 4);
    // 5. u = gelu(x @ mW1^T + mb1), stored fp16
    mma_gemm<1><<<dim3(F / 128, S / 128, Bsz), 256, SMEM_BYTES>>>(nullptr, nullptr, nullptr);
    // 6. out = u @ mW2^T + mb2
    mma_gemm<2><<<dim3(H / 128, S / 128, Bsz), 256, SMEM_BYTES>>>(nullptr, nullptr, out);
}